// round 13
// baseline (speedup 1.0000x reference)
#include <cuda_runtime.h>

// DistanceTransformMap: exact EDT + approx-sqrt (rel err ~2^-23 << 1e-3).
// SINGLE kernel: phase 1 non-redundant ballot-compress into transposed
// bitmap -> one grid barrier -> phase 2 funnels + column search.
// R13: searches take 4 CONSECUTIVE y per thread so the four d<=4 windows
// load as 3 aligned LDS.128 (12 contiguous floats) instead of 36 scalar LDS.
//
// Exactness of the EDT (before sqrt):
//  - funnel covers >=33 bits each direction; empty window -> exact word loop;
//    zero word-pads make boundaries exact; no zero in row -> d>=384 -> LARGE
//    (matches reference: min attained at j=i is LARGE).
//  - near window d<=4 unconditional: extra candidates are upper bounds.
//  - far case (best>25): clamped indices land on LARGE pads (left slots 0..7,
//    right 392..399); LARGE + d^2 > LARGE >= best0 never wins.
// All EDT intermediates are exact integers < 2^24 in fp32.
// Barrier: monotonic counter, grid=384 all wave-1 resident at occ 3 ->
// deadlock-free; monotonicity -> correct across CUDA-graph replays.

constexpr int Bn = 4;
constexpr int Hn = 384;
constexpr int Wn = 384;
constexpr int N  = 384;
constexpr int JW = 14;                        // 12 words + 2 zero pads
constexpr float LARGE = 2.0f * (float)(Hn * Hn + Wn * Wn);  // 589824 > 383^2

constexpr int PAD = 8;
constexpr int LWD = N + 2 * PAD;              // 400 valid slots
constexpr int LWP = 404;                      // line stride (16B-aligned lines)
constexpr int CPB = 4;
constexpr int NT  = 384;
constexpr int GRID = Bn * (Wn / CPB);         // 384

__device__ unsigned g_bm_t[Bn * JW * Hn];
__device__ unsigned g_bar;

__device__ __forceinline__ float sqrt_approx(float x) {
    float r;
    asm("sqrt.approx.f32 %0, %1;" : "=f"(r) : "f"(x));
    return r;
}

__device__ __forceinline__ float near_far(const float* __restrict__ row,
                                          float best, int i) {
    // row points at line base (slot 0); element i lives at row[PAD + i].
    float df = 5.0f;
    int d = 5;
    const int ip = i + PAD;
    while (df * df < best && d < N) {
#pragma unroll
        for (int u = 0; u < 4; ++u) {
            const int jr = min(ip + d + u, LWD - 1);
            const int jl = max(ip - d - u, 0);
            const float e = df + (float)u;
            best = fminf(best, fmaf(e, e, fminf(row[jr], row[jl])));
        }
        df += 4.0f;
        d += 4;
    }
    return best;
}

__device__ __forceinline__ void grid_barrier() {
    __threadfence();
    __syncthreads();
    if (threadIdx.x == 0) {
        const unsigned old = atomicAdd(&g_bar, 1u);
        const unsigned target = old - (old % GRID) + GRID;
        while (atomicAdd(&g_bar, 0u) < target) {
            __nanosleep(64);
        }
        __threadfence();
    }
    __syncthreads();
}

__global__ __launch_bounds__(NT, 3) void edt_all(const float* __restrict__ mask,
                                                 float* __restrict__ out) {
    __shared__ unsigned sh_t[3 * Hn];                 // word-slabs [q][y]
    __shared__ __align__(16) float lines[CPB * LWP];  // padded column-lines
    __shared__ float sh_o[Hn * 5];                    // output stage [y][c]

    const int t = threadIdx.x;
    const int w = t >> 5, lane = t & 31;

    // ---- Phase 1: compress 4 rows per block (non-redundant) ----
    {
        const int row_k = w & 3;
        const int grp = w >> 2;                // words 4g..4g+3
        const int L = blockIdx.x * 4 + row_k;
        const int b1 = L / Hn, y1 = L - b1 * Hn;
        unsigned* __restrict__ dstb = g_bm_t + (size_t)b1 * JW * Hn;
        const float* __restrict__ srow = mask + (size_t)L * N;
#pragma unroll
        for (int u = 0; u < 4; ++u) {
            const int j = grp * 4 + u;
            const float v = srow[j * 32 + lane];
            const unsigned m = __ballot_sync(0xffffffffu, v <= 0.5f);
            if (lane == j) dstb[(j + 1) * Hn + y1] = m;
        }
        if (grp == 0) {
            if (lane == 12) dstb[y1] = 0u;
            if (lane == 13) dstb[13 * Hn + y1] = 0u;
        }
    }

    grid_barrier();

    // ---- Phase 2 ----
    const int b = blockIdx.x / (Wn / CPB);
    const int x0 = (blockIdx.x - b * (Wn / CPB)) * CPB;
    const int jw = x0 >> 5;

    const unsigned* __restrict__ src = g_bm_t + ((size_t)b * JW + jw) * Hn;
#pragma unroll
    for (int r = 0; r < 3; ++r)
        sh_t[t + NT * r] = src[t + NT * r];
    if (t < CPB * PAD) {
        const int c = t >> 3, o = t & 7;
        lines[c * LWP + o] = LARGE;
        lines[c * LWP + LWD - PAD + o] = LARGE;
    }
    __syncthreads();

    {   // row distances: thread owns y=t, CPB columns via funnels
        const int y = t;
        const unsigned wm1 = sh_t[y];
        const unsigned w0  = sh_t[Hn + y];
        const unsigned wp1 = sh_t[2 * Hn + y];
        const unsigned long long vr = ((unsigned long long)wp1 << 32) | w0;
        const unsigned long long vl = ((unsigned long long)w0 << 32) | wm1;
        const int bp0 = x0 & 31;
        const unsigned* __restrict__ gfb = g_bm_t + (size_t)b * JW * Hn;
#pragma unroll
        for (int xl = 0; xl < CPB; ++xl) {
            const int bp = bp0 + xl;           // <= 31
            const int xg = x0 + xl;
            int dr, dl;
            const unsigned long long r64 = vr >> bp;
            if (r64) {
                dr = __ffsll(r64) - 1;
            } else {                            // rare exact fallback
                dr = 0x7fff;
                for (int j = jw + 2; j < 12; ++j) {
                    const unsigned uu = gfb[(j + 1) * Hn + y];
                    if (uu) { dr = j * 32 - xg + __ffs(uu) - 1; break; }
                }
            }
            const unsigned long long l64 = vl << (31 - bp);
            if (l64) {
                dl = __clzll(l64);
            } else {
                dl = 0x7fff;
                for (int j = jw - 2; j >= 0; --j) {
                    const unsigned uu = gfb[(j + 1) * Hn + y];
                    if (uu) { dl = xg - j * 32 - 31 + __clz(uu); break; }
                }
            }
            const int d = min(dl, dr);
            lines[xl * LWP + PAD + y] = (d < 384) ? (float)(d * d) : LARGE;
        }
    }
    __syncthreads();

    // ---- Column search: blocked y (4 consecutive per thread) ----
    const int cl = w & 3, seg = w >> 2;
    const float* __restrict__ row = &lines[cl * LWP];
    const int i0 = seg * 32 + lane;            // 0..95; y0 = 4*i0

    // 12 contiguous floats covering y0-4 .. y0+7 (16B-aligned: PAD-4+4*i0).
    const float4* __restrict__ vp =
        reinterpret_cast<const float4*>(row + PAD - 4 + 4 * i0);
    const float4 A = vp[0], Bq = vp[1], Cq = vp[2];
    const float v[12] = {A.x, A.y, A.z, A.w, Bq.x, Bq.y, Bq.z, Bq.w,
                         Cq.x, Cq.y, Cq.z, Cq.w};

    float best[4];
#pragma unroll
    for (int k = 0; k < 4; ++k) {              // search at y = 4*i0 + k
        const float c1 = fminf(v[k + 3], v[k + 5]) + 1.0f;
        const float c2 = fminf(v[k + 2], v[k + 6]) + 4.0f;
        const float c3 = fminf(v[k + 1], v[k + 7]) + 9.0f;
        const float c4 = fminf(v[k + 0], v[k + 8]) + 16.0f;
        best[k] = fminf(v[k + 4], fminf(fminf(c1, c2), fminf(c3, c4)));
    }
    const float gmax = fmaxf(fmaxf(best[0], best[1]), fmaxf(best[2], best[3]));
    if (gmax > 25.0f) {                        // rare: refine the ones that need it
#pragma unroll
        for (int k = 0; k < 4; ++k)
            if (best[k] > 25.0f)
                best[k] = near_far(row, best[k], 4 * i0 + k);
    }

#pragma unroll
    for (int k = 0; k < 4; ++k)
        sh_o[(4 * i0 + k) * 5 + cl] = sqrt_approx(best[k]);
    __syncthreads();

    // ---- Tile store: 4 consecutive floats per y ----
    const int c_st = t & 3, y_st = t >> 2;
    float* __restrict__ dst = out + ((size_t)b * Hn) * Wn + x0 + c_st;
#pragma unroll
    for (int r = 0; r < 4; ++r) {
        const int y = y_st + 96 * r;
        dst[(size_t)y * Wn] = sh_o[y * 5 + c_st];
    }
}

extern "C" void kernel_launch(void* const* d_in, const int* in_sizes, int n_in,
                              void* d_out, int out_size) {
    const float* mask = (const float*)d_in[0];
    float* out = (float*)d_out;
    (void)in_sizes; (void)n_in; (void)out_size;

    edt_all<<<GRID, NT>>>(mask, out);
}

// round 14
// speedup vs baseline: 1.0238x; 1.0238x over previous
#include <cuda_runtime.h>

// DistanceTransformMap: exact EDT + approx-sqrt (rel err ~2^-23 << 1e-3).
// SINGLE kernel: phase 1 non-redundant ballot-compress into transposed
// bitmap -> PER-BATCH grid barrier (flag-spin, no RMW polling) -> phase 2
// funnels + column search (R13 search: 3x LDS.128 blocked-y windows).
//
// Barrier rationale (R14): R13's single-counter barrier polled with
// atomicAdd(addr,0); 384 concurrent RMWs at one address serialize in the
// LTS atomic ALU (~10k cycles of wall time). Now: one arrival atomicAdd per
// block on a per-batch counter (96 blocks/group), last arriver publishes a
// monotonic generation flag (atomicMax -> replay-safe), everyone else spins
// on a volatile LOAD (no ALU serialization). Blocks 96b..96b+95 both produce
// and consume batch b's bitmap, so per-batch grouping is dependency-exact.
// grid=384 at occ 3 -> all wave-1 resident -> deadlock-free.
//
// Exactness of the EDT (before sqrt):
//  - funnel covers >=33 bits each direction; empty window -> exact word loop;
//    zero word-pads make boundaries exact; no zero in row -> d>=384 -> LARGE
//    (matches reference: min attained at j=i is LARGE).
//  - near window d<=4 unconditional: extra candidates are upper bounds.
//  - far case (best>25): clamped indices land on LARGE pads (left slots 0..7,
//    right 392..399); LARGE + d^2 > LARGE >= best0 never wins.
// All EDT intermediates are exact integers < 2^24 in fp32.

constexpr int Bn = 4;
constexpr int Hn = 384;
constexpr int Wn = 384;
constexpr int N  = 384;
constexpr int JW = 14;                        // 12 words + 2 zero pads
constexpr float LARGE = 2.0f * (float)(Hn * Hn + Wn * Wn);  // 589824 > 383^2

constexpr int PAD = 8;
constexpr int LWD = N + 2 * PAD;              // 400 valid slots
constexpr int LWP = 404;                      // line stride (16B-aligned lines)
constexpr int CPB = 4;
constexpr int NT  = 384;
constexpr int SPB = Wn / CPB;                 // 96 strips (= blocks) per batch
constexpr int GRID = Bn * SPB;                // 384

__device__ unsigned g_bm_t[Bn * JW * Hn];
__device__ unsigned g_cnt[Bn];                // per-batch arrival counters
__device__ unsigned g_flag[Bn];               // per-batch generation flags

__device__ __forceinline__ float sqrt_approx(float x) {
    float r;
    asm("sqrt.approx.f32 %0, %1;" : "=f"(r) : "f"(x));
    return r;
}

__device__ __forceinline__ float near_far(const float* __restrict__ row,
                                          float best, int i) {
    float df = 5.0f;
    int d = 5;
    const int ip = i + PAD;
    while (df * df < best && d < N) {
#pragma unroll
        for (int u = 0; u < 4; ++u) {
            const int jr = min(ip + d + u, LWD - 1);
            const int jl = max(ip - d - u, 0);
            const float e = df + (float)u;
            best = fminf(best, fmaf(e, e, fminf(row[jr], row[jl])));
        }
        df += 4.0f;
        d += 4;
    }
    return best;
}

// Per-batch barrier: counter arrival + flag spin on plain volatile loads.
__device__ __forceinline__ void batch_barrier(int bb) {
    __threadfence();                           // publish my bitmap stores
    __syncthreads();
    if (threadIdx.x == 0) {
        const unsigned old = atomicAdd(&g_cnt[bb], 1u);
        const unsigned target = old / (unsigned)SPB + 1u;   // this call's generation
        if ((old % (unsigned)SPB) == (unsigned)(SPB - 1)) {
            atomicMax(&g_flag[bb], target);    // monotonic publish
        } else {
            const volatile unsigned* f = (const volatile unsigned*)&g_flag[bb];
            while (*f < target) { __nanosleep(32); }
        }
        __threadfence();                       // acquire side
    }
    __syncthreads();
}

__global__ __launch_bounds__(NT, 3) void edt_all(const float* __restrict__ mask,
                                                 float* __restrict__ out) {
    __shared__ unsigned sh_t[3 * Hn];                 // word-slabs [q][y]
    __shared__ __align__(16) float lines[CPB * LWP];  // padded column-lines
    __shared__ float sh_o[Hn * 5];                    // output stage [y][c]

    const int t = threadIdx.x;
    const int w = t >> 5, lane = t & 31;
    const int b = blockIdx.x / SPB;            // batch (phase 1 AND phase 2)
    const int x0 = (blockIdx.x - b * SPB) * CPB;

    // ---- Phase 1: compress 4 rows of my batch (non-redundant) ----
    {
        const int row_k = w & 3;
        const int grp = w >> 2;                // words 4g..4g+3
        const int L = blockIdx.x * 4 + row_k;  // rows 384b .. 384b+383
        const int y1 = L - b * Hn;
        unsigned* __restrict__ dstb = g_bm_t + (size_t)b * JW * Hn;
        const float* __restrict__ srow = mask + (size_t)L * N;
#pragma unroll
        for (int u = 0; u < 4; ++u) {
            const int j = grp * 4 + u;
            const float v = srow[j * 32 + lane];
            const unsigned m = __ballot_sync(0xffffffffu, v <= 0.5f);
            if (lane == j) dstb[(j + 1) * Hn + y1] = m;
        }
        if (grp == 0) {
            if (lane == 12) dstb[y1] = 0u;
            if (lane == 13) dstb[13 * Hn + y1] = 0u;
        }
    }
    // Overlap: LARGE pads for column lines (local smem, independent of barrier).
    if (t < CPB * PAD) {
        const int c = t >> 3, o = t & 7;
        lines[c * LWP + o] = LARGE;
        lines[c * LWP + LWD - PAD + o] = LARGE;
    }

    batch_barrier(b);                          // batch b's bitmap visible

    // ---- Phase 2 ----
    const int jw = x0 >> 5;
    const unsigned* __restrict__ src = g_bm_t + ((size_t)b * JW + jw) * Hn;
#pragma unroll
    for (int r = 0; r < 3; ++r)
        sh_t[t + NT * r] = src[t + NT * r];    // contiguous, L2-hot
    __syncthreads();

    {   // row distances: thread owns y=t, CPB columns via funnels
        const int y = t;
        const unsigned wm1 = sh_t[y];
        const unsigned w0  = sh_t[Hn + y];
        const unsigned wp1 = sh_t[2 * Hn + y];
        const unsigned long long vr = ((unsigned long long)wp1 << 32) | w0;
        const unsigned long long vl = ((unsigned long long)w0 << 32) | wm1;
        const int bp0 = x0 & 31;
        const unsigned* __restrict__ gfb = g_bm_t + (size_t)b * JW * Hn;
#pragma unroll
        for (int xl = 0; xl < CPB; ++xl) {
            const int bp = bp0 + xl;           // <= 31
            const int xg = x0 + xl;
            int dr, dl;
            const unsigned long long r64 = vr >> bp;
            if (r64) {
                dr = __ffsll(r64) - 1;
            } else {                            // rare exact fallback
                dr = 0x7fff;
                for (int j = jw + 2; j < 12; ++j) {
                    const unsigned uu = gfb[(j + 1) * Hn + y];
                    if (uu) { dr = j * 32 - xg + __ffs(uu) - 1; break; }
                }
            }
            const unsigned long long l64 = vl << (31 - bp);
            if (l64) {
                dl = __clzll(l64);
            } else {
                dl = 0x7fff;
                for (int j = jw - 2; j >= 0; --j) {
                    const unsigned uu = gfb[(j + 1) * Hn + y];
                    if (uu) { dl = xg - j * 32 - 31 + __clz(uu); break; }
                }
            }
            const int d = min(dl, dr);
            lines[xl * LWP + PAD + y] = (d < 384) ? (float)(d * d) : LARGE;
        }
    }
    __syncthreads();

    // ---- Column search: blocked y, 4 consecutive per thread, 3x LDS.128 ----
    const int cl = w & 3, seg = w >> 2;
    const float* __restrict__ row = &lines[cl * LWP];
    const int i0 = seg * 32 + lane;            // 0..95; y0 = 4*i0

    const float4* __restrict__ vp =
        reinterpret_cast<const float4*>(row + PAD - 4 + 4 * i0);
    const float4 A = vp[0], Bq = vp[1], Cq = vp[2];
    const float v[12] = {A.x, A.y, A.z, A.w, Bq.x, Bq.y, Bq.z, Bq.w,
                         Cq.x, Cq.y, Cq.z, Cq.w};

    float best[4];
#pragma unroll
    for (int k = 0; k < 4; ++k) {
        const float c1 = fminf(v[k + 3], v[k + 5]) + 1.0f;
        const float c2 = fminf(v[k + 2], v[k + 6]) + 4.0f;
        const float c3 = fminf(v[k + 1], v[k + 7]) + 9.0f;
        const float c4 = fminf(v[k + 0], v[k + 8]) + 16.0f;
        best[k] = fminf(v[k + 4], fminf(fminf(c1, c2), fminf(c3, c4)));
    }
    const float gmax = fmaxf(fmaxf(best[0], best[1]), fmaxf(best[2], best[3]));
    if (gmax > 25.0f) {
#pragma unroll
        for (int k = 0; k < 4; ++k)
            if (best[k] > 25.0f)
                best[k] = near_far(row, best[k], 4 * i0 + k);
    }

#pragma unroll
    for (int k = 0; k < 4; ++k)
        sh_o[(4 * i0 + k) * 5 + cl] = sqrt_approx(best[k]);
    __syncthreads();

    // ---- Tile store: 4 consecutive floats per y ----
    const int c_st = t & 3, y_st = t >> 2;
    float* __restrict__ dst = out + ((size_t)b * Hn) * Wn + x0 + c_st;
#pragma unroll
    for (int r = 0; r < 4; ++r) {
        const int y = y_st + 96 * r;
        dst[(size_t)y * Wn] = sh_o[y * 5 + c_st];
    }
}

extern "C" void kernel_launch(void* const* d_in, const int* in_sizes, int n_in,
                              void* d_out, int out_size) {
    const float* mask = (const float*)d_in[0];
    float* out = (float*)d_out;
    (void)in_sizes; (void)n_in; (void)out_size;

    edt_all<<<GRID, NT>>>(mask, out);
}